// round 7
// baseline (speedup 1.0000x reference)
#include <cuda_runtime.h>
#include <cuda_fp16.h>
#include <cstdint>

// ============================ problem constants ============================
#define BB 4
#define NN 4096
#define FF 128
#define KT 32                    // K per pipeline stage
#define NSTG 7
#define KITERS (NN / KT)         // 128

// ====================== main-kernel smem layout (bytes) ===================
// A stage: 128 rows x 40 floats (32 data + 8 pad) = 20480 B
// B stage: 128 rows x 40 halves (32 data + 8 pad) = 10240 B
#define SM_DEG    0
#define SM_STG    512
#define STG_BYT   30720
#define SM_A(s)   (SM_STG + (s) * STG_BYT)
#define SM_B(s)   (SM_A(s) + 20480)
#define SMEM_MAIN (SM_STG + NSTG * STG_BYT)        // 215552 B

// scratch (allocation-free rule: __device__ globals)
__device__ __align__(16) __half g_xw [(size_t)BB * NN * FF];  // Xw[b][k][n]
__device__ __align__(16) __half g_xwt[(size_t)BB * FF * NN];  // Xwt[b][n][k]

// ============================ helpers ============================
__device__ __forceinline__ uint32_t smem_to_u32(const void* p) {
    uint32_t a;
    asm("{ .reg .u64 tmp; cvta.to.shared.u64 tmp, %1; cvt.u32.u64 %0, tmp; }"
        : "=r"(a) : "l"(p));
    return a;
}

__device__ __forceinline__ void cp16(uint32_t s, const void* g) {
    asm volatile("cp.async.cg.shared.global [%0], [%1], 16;" :: "r"(s), "l"(g));
}

// pack two fp32 -> f16x2 reg, lo in low half (round-to-nearest-even)
__device__ __forceinline__ uint32_t packh2(float lo, float hi) {
    uint32_t r;
    asm("cvt.rn.f16x2.f32 %0, %1, %2;" : "=r"(r) : "f"(hi), "f"(lo));
    return r;
}

// D += A(16x16) * B(16x8), fp16 inputs, fp32 accum
#define MMA16(d, a, b) \
    asm volatile("mma.sync.aligned.m16n8k16.row.col.f32.f16.f16.f32 " \
        "{%0,%1,%2,%3}, {%4,%5,%6,%7}, {%8,%9}, {%0,%1,%2,%3};" \
        : "+f"((d)[0]), "+f"((d)[1]), "+f"((d)[2]), "+f"((d)[3]) \
        : "r"((a)[0]), "r"((a)[1]), "r"((a)[2]), "r"((a)[3]), \
          "r"((b)[0]), "r"((b)[1]))

// ============================ prep kernel ============================
// Xw = X @ w (fp16 mma, fp32 accum) for one 128-row k-tile; writes both
// layouts: g_xw[b][k][n] and g_xwt[b][n][k] (fp16).
// grid (32, BB), 512 threads = 16 warps (4x4), warp tile 32(k) x 32(n).
#define PX_STRIDE 136            // halves per row (128 data + 8 pad)
#define TS_STRIDE 130            // transpose staging stride (conflict-free)
__global__ void __launch_bounds__(512, 1)
prep_xw_kernel(const float* __restrict__ X, const float* __restrict__ w) {
    extern __shared__ __align__(16) char psm[];
    __half* smx = reinterpret_cast<__half*>(psm);                   // X tile
    __half* smw = reinterpret_cast<__half*>(psm) + 128 * PX_STRIDE; // wt[n][f]
    const int tid = threadIdx.x;
    const int lane = tid & 31, warp = tid >> 5;
    const int g = lane >> 2, t = lane & 3;
    const int wr = warp >> 2, wc = warp & 3;
    const int b = blockIdx.y, k0 = blockIdx.x * 128;

    // X tile -> fp16 smem (row-major [k][f])
    const float2* xp = reinterpret_cast<const float2*>(
        X + ((size_t)b * NN + k0) * FF);
    #pragma unroll
    for (int i = 0; i < 16; i++) {
        int idx = tid + 512 * i;             // 8192 float2
        int k = idx >> 6, f2i = idx & 63;
        float2 v = xp[(size_t)k * 64 + f2i];
        *reinterpret_cast<__half2*>(smx + k * PX_STRIDE + f2i * 2) =
            __float22half2_rn(v);
    }
    // w -> fp16 smem transposed (wt[n][f] = w[f][n])
    #pragma unroll
    for (int i = 0; i < 16; i++) {
        int idx = tid + 512 * i;             // 8192 float2
        int f = idx >> 6, n = (idx & 63) * 2;
        float2 v = *reinterpret_cast<const float2*>(w + (size_t)f * FF + n);
        smw[(n + 0) * PX_STRIDE + f] = __float2half_rn(v.x);
        smw[(n + 1) * PX_STRIDE + f] = __float2half_rn(v.y);
    }
    __syncthreads();

    float acc[2][4][4];
    #pragma unroll
    for (int mi = 0; mi < 2; mi++)
        #pragma unroll
        for (int ni = 0; ni < 4; ni++)
            #pragma unroll
            for (int q = 0; q < 4; q++) acc[mi][ni][q] = 0.f;

    #pragma unroll
    for (int ks = 0; ks < 8; ks++) {
        const int kk = ks * 16;
        uint32_t af[2][4];
        #pragma unroll
        for (int mi = 0; mi < 2; mi++) {
            const __half* ap = smx + (wr * 32 + mi * 16 + g) * PX_STRIDE + kk + 2 * t;
            af[mi][0] = *reinterpret_cast<const uint32_t*>(ap);
            af[mi][1] = *reinterpret_cast<const uint32_t*>(ap + 8 * PX_STRIDE);
            af[mi][2] = *reinterpret_cast<const uint32_t*>(ap + 8);
            af[mi][3] = *reinterpret_cast<const uint32_t*>(ap + 8 * PX_STRIDE + 8);
        }
        uint32_t bf[4][2];
        #pragma unroll
        for (int ni = 0; ni < 4; ni++) {
            const __half* bp = smw + (wc * 32 + ni * 8 + g) * PX_STRIDE + kk + 2 * t;
            bf[ni][0] = *reinterpret_cast<const uint32_t*>(bp);
            bf[ni][1] = *reinterpret_cast<const uint32_t*>(bp + 8);
        }
        #pragma unroll
        for (int mi = 0; mi < 2; mi++)
            #pragma unroll
            for (int ni = 0; ni < 4; ni++)
                MMA16(acc[mi][ni], af[mi], bf[ni]);
    }

    // write Xw[b][k][n] (fp16, coalesced) and stage for transpose
    __half* xwg = g_xw + ((size_t)b * NN + k0) * FF;
    __syncthreads();                         // done reading smx -> reuse as stg
    __half* stg = smx;                       // [k][n], stride TS_STRIDE
    #pragma unroll
    for (int mi = 0; mi < 2; mi++) {
        int r0 = wr * 32 + mi * 16 + g;
        #pragma unroll
        for (int ni = 0; ni < 4; ni++) {
            int n = wc * 32 + ni * 8 + 2 * t;
            __half2 h0 = __floats2half2_rn(acc[mi][ni][0], acc[mi][ni][1]);
            __half2 h1 = __floats2half2_rn(acc[mi][ni][2], acc[mi][ni][3]);
            *reinterpret_cast<__half2*>(xwg + (size_t)r0 * FF + n) = h0;
            *reinterpret_cast<__half2*>(xwg + (size_t)(r0 + 8) * FF + n) = h1;
            stg[r0 * TS_STRIDE + n] = __low2half(h0);
            stg[r0 * TS_STRIDE + n + 1] = __high2half(h0);
            stg[(r0 + 8) * TS_STRIDE + n] = __low2half(h1);
            stg[(r0 + 8) * TS_STRIDE + n + 1] = __high2half(h1);
        }
    }
    __syncthreads();
    // transposed write Xwt[b][n][k0+kk] (stride-130 staging: conflict-free)
    __half* xwtg = g_xwt + (size_t)b * FF * NN + k0;
    #pragma unroll
    for (int i = 0; i < 32; i++) {
        int idx = tid + 512 * i;             // 16384 halves
        int n = idx >> 7, kk = idx & 127;
        xwtg[(size_t)n * NN + kk] = stg[kk * TS_STRIDE + n];
    }
}

// ============================ main kernel ============================
// grid = 128 CTAs (4 batches x 32 M-tiles), 512 threads = 16 warps (4x4),
// warp tile 32(M) x 32(N). cp.async 7-stage pipeline, mma.sync fp16 k16.
__global__ void __launch_bounds__(512, 1)
graphconv_main(const float* __restrict__ A, float* __restrict__ out) {
    extern __shared__ __align__(16) char smc[];
    float* sm = reinterpret_cast<float*>(smc);
    const uint32_t sbase = smem_to_u32(smc);
    const int tid = threadIdx.x;
    const int lane = tid & 31, warp = tid >> 5;
    const int g = lane >> 2, t = lane & 3;
    const int wr = warp >> 2, wc = warp & 3;      // warp grid 4(M) x 4(N)
    const int bb = blockIdx.x >> 5;
    const int row0 = (blockIdx.x & 31) << 7;

    const float* Ab = A + (size_t)bb * NN * NN + (size_t)row0 * NN;
    const __half* Xwt = g_xwt + (size_t)bb * FF * NN;

    auto issue = [&](int chunk, int s) {
        const int k0 = chunk * KT;
        #pragma unroll
        for (int i = 0; i < 2; i++) {        // A: 128 rows x 128 B
            int c = tid + 512 * i, r = c >> 3, cc = c & 7;
            cp16(sbase + SM_A(s) + r * 160 + cc * 16,
                 Ab + (size_t)r * NN + k0 + cc * 4);
        }
        {                                    // B: 128 rows x 64 B (fp16)
            int r = tid >> 2, cc = tid & 3;
            cp16(sbase + SM_B(s) + r * 80 + cc * 16,
                 Xwt + (size_t)r * NN + k0 + cc * 8);
        }
        asm volatile("cp.async.commit_group;");
    };

    float acc[2][4][4];
    #pragma unroll
    for (int mi = 0; mi < 2; mi++)
        #pragma unroll
        for (int ni = 0; ni < 4; ni++)
            #pragma unroll
            for (int q = 0; q < 4; q++) acc[mi][ni][q] = 0.f;

    float dsum = 0.f;
    const int drow = tid >> 2, dq = tid & 3;

    #pragma unroll
    for (int p = 0; p < NSTG - 1; p++) issue(p, p);

    int s = 0, s6 = NSTG - 1;
    for (int k = 0; k < KITERS; k++) {
        asm volatile("cp.async.wait_group %0;" :: "n"(NSTG - 2));
        __syncthreads();

        if (k + NSTG - 1 < KITERS) issue(k + NSTG - 1, s6);
        else asm volatile("cp.async.commit_group;");   // keep group count rolling

        const float* sa = sm + (SM_A(s) >> 2);
        const __half* sb = reinterpret_cast<const __half*>(smc + SM_B(s));

        // deg partial row-sum (raw fp32 A) — quarter row per thread
        {
            const float4* dp =
                reinterpret_cast<const float4*>(sa + drow * 40 + dq * 8);
            float4 v0 = dp[0], v1 = dp[1];
            dsum += ((v0.x + v0.y) + (v0.z + v0.w)) +
                    ((v1.x + v1.y) + (v1.z + v1.w));
        }

        #pragma unroll
        for (int ks = 0; ks < 2; ks++) {
            const int kk = ks * 16;
            uint32_t af[2][4];
            #pragma unroll
            for (int mi = 0; mi < 2; mi++) {
                const float* ap = sa + (wr * 32 + mi * 16 + g) * 40 + kk + 2 * t;
                float2 v0 = *reinterpret_cast<const float2*>(ap);
                float2 v1 = *reinterpret_cast<const float2*>(ap + 8 * 40);
                float2 v2 = *reinterpret_cast<const float2*>(ap + 8);
                float2 v3 = *reinterpret_cast<const float2*>(ap + 8 * 40 + 8);
                af[mi][0] = packh2(v0.x, v0.y);
                af[mi][1] = packh2(v1.x, v1.y);
                af[mi][2] = packh2(v2.x, v2.y);
                af[mi][3] = packh2(v3.x, v3.y);
            }
            uint32_t bf[4][2];
            #pragma unroll
            for (int ni = 0; ni < 4; ni++) {
                const __half* bp = sb + (wc * 32 + ni * 8 + g) * 40 + kk + 2 * t;
                bf[ni][0] = *reinterpret_cast<const uint32_t*>(bp);
                bf[ni][1] = *reinterpret_cast<const uint32_t*>(bp + 8);
            }
            #pragma unroll
            for (int mi = 0; mi < 2; mi++)
                #pragma unroll
                for (int ni = 0; ni < 4; ni++)
                    MMA16(acc[mi][ni], af[mi], bf[ni]);
        }

        if (++s == NSTG) s = 0;
        if (++s6 == NSTG) s6 = 0;
    }

    // deg = rowsum(A) + 1 ; store reciprocal
    dsum += __shfl_xor_sync(0xffffffffu, dsum, 1);
    dsum += __shfl_xor_sync(0xffffffffu, dsum, 2);
    if (dq == 0) sm[(SM_DEG >> 2) + drow] = 1.0f / (dsum + 1.0f);
    __syncthreads();

    // out = relu(acc + Xw) * (1/deg)
    {
        float rc[2][2];
        #pragma unroll
        for (int mi = 0; mi < 2; mi++) {
            rc[mi][0] = sm[(SM_DEG >> 2) + wr * 32 + mi * 16 + g];
            rc[mi][1] = sm[(SM_DEG >> 2) + wr * 32 + mi * 16 + g + 8];
        }
        const __half* xwb = g_xw + ((size_t)bb * NN + row0) * FF;
        float* ob = out + ((size_t)bb * NN + row0) * FF;
        #pragma unroll
        for (int mi = 0; mi < 2; mi++) {
            int r0 = wr * 32 + mi * 16 + g;
            #pragma unroll
            for (int ni = 0; ni < 4; ni++) {
                int n = wc * 32 + ni * 8 + 2 * t;
                float2 x0 = __half22float2(*reinterpret_cast<const __half2*>(
                    xwb + (size_t)r0 * FF + n));
                float2 x1 = __half22float2(*reinterpret_cast<const __half2*>(
                    xwb + (size_t)(r0 + 8) * FF + n));
                float2 v0, v1;
                v0.x = fmaxf(acc[mi][ni][0] + x0.x, 0.f) * rc[mi][0];
                v0.y = fmaxf(acc[mi][ni][1] + x0.y, 0.f) * rc[mi][0];
                v1.x = fmaxf(acc[mi][ni][2] + x1.x, 0.f) * rc[mi][1];
                v1.y = fmaxf(acc[mi][ni][3] + x1.y, 0.f) * rc[mi][1];
                *reinterpret_cast<float2*>(ob + (size_t)r0 * FF + n) = v0;
                *reinterpret_cast<float2*>(ob + (size_t)(r0 + 8) * FF + n) = v1;
            }
        }
    }
}

// ============================ host ============================
extern "C" void kernel_launch(void* const* d_in, const int* in_sizes, int n_in,
                              void* d_out, int out_size) {
    const float* A = (const float*)d_in[0];   // relation_matrix [4,4096,4096]
    const float* X = (const float*)d_in[1];   // inputs          [4,4096,128]
    const float* w = (const float*)d_in[2];   // w               [128,128]
    float* out = (float*)d_out;               // [4,4096,128] fp32

    const int prep_smem = 2 * 128 * PX_STRIDE * 2;   // 69632 B
    cudaFuncSetAttribute(prep_xw_kernel,
                         cudaFuncAttributeMaxDynamicSharedMemorySize, prep_smem);
    cudaFuncSetAttribute(graphconv_main,
                         cudaFuncAttributeMaxDynamicSharedMemorySize, SMEM_MAIN);

    prep_xw_kernel<<<dim3(NN / 128, BB), 512, prep_smem>>>(X, w);
    graphconv_main<<<BB * 32, 512, SMEM_MAIN>>>(A, out);
}

// round 8
// speedup vs baseline: 1.6992x; 1.6992x over previous
#include <cuda_runtime.h>
#include <cuda_fp16.h>
#include <cstdint>

// ============================ problem constants ============================
#define BB 4
#define NN 4096
#define FF 128
#define KT 32                    // K per pipeline stage
#define NSTG 5
#define KITERS (NN / KT)         // 128
#define MT 64                    // M rows per CTA

// ====================== main-kernel smem layout (bytes) ===================
// A stage: 64 rows x 40 floats (32 data + 8 pad) = 10240 B
// B stage: 128 rows x 40 halves (32 data + 8 pad) = 10240 B
#define SM_DEG    0
#define SM_STG    512
#define STG_BYT   20480
#define SM_A(s)   (SM_STG + (s) * STG_BYT)
#define SM_B(s)   (SM_A(s) + 10240)
#define SMEM_MAIN (SM_STG + NSTG * STG_BYT)        // 102912 B -> 2 CTAs/SM

// scratch (allocation-free rule: __device__ globals)
__device__ __align__(16) __half g_xw [(size_t)BB * NN * FF];  // Xw[b][k][n]
__device__ __align__(16) __half g_xwt[(size_t)BB * FF * NN];  // Xwt[b][n][k]

// ============================ helpers ============================
__device__ __forceinline__ uint32_t smem_to_u32(const void* p) {
    uint32_t a;
    asm("{ .reg .u64 tmp; cvta.to.shared.u64 tmp, %1; cvt.u32.u64 %0, tmp; }"
        : "=r"(a) : "l"(p));
    return a;
}

__device__ __forceinline__ void cp16(uint32_t s, const void* g) {
    asm volatile("cp.async.cg.shared.global [%0], [%1], 16;" :: "r"(s), "l"(g));
}

// pack two fp32 -> f16x2 reg, lo in low half (round-to-nearest-even)
__device__ __forceinline__ uint32_t packh2(float lo, float hi) {
    uint32_t r;
    asm("cvt.rn.f16x2.f32 %0, %1, %2;" : "=r"(r) : "f"(hi), "f"(lo));
    return r;
}

// D += A(16x16) * B(16x8), fp16 inputs, fp32 accum
#define MMA16(d, a, b) \
    asm volatile("mma.sync.aligned.m16n8k16.row.col.f32.f16.f16.f32 " \
        "{%0,%1,%2,%3}, {%4,%5,%6,%7}, {%8,%9}, {%0,%1,%2,%3};" \
        : "+f"((d)[0]), "+f"((d)[1]), "+f"((d)[2]), "+f"((d)[3]) \
        : "r"((a)[0]), "r"((a)[1]), "r"((a)[2]), "r"((a)[3]), \
          "r"((b)[0]), "r"((b)[1]))

// ============================ prep kernel (R5 proven) =====================
// Xw = X @ w (fp16 mma, fp32 accum); writes g_xw[b][k][n] and g_xwt[b][n][k].
// grid (32, BB), 256 threads = 8 warps (4x2), warp tile 32(k) x 64(n).
#define PX_STRIDE 136            // halves per row (128 data + 8 pad)
__global__ void __launch_bounds__(256, 1)
prep_xw_kernel(const float* __restrict__ X, const float* __restrict__ w) {
    extern __shared__ __align__(16) char psm[];
    __half* smx = reinterpret_cast<__half*>(psm);                   // X tile
    __half* smw = reinterpret_cast<__half*>(psm) + 128 * PX_STRIDE; // wt[n][f]
    const int tid = threadIdx.x;
    const int lane = tid & 31, warp = tid >> 5;
    const int g = lane >> 2, t = lane & 3;
    const int wr = warp >> 1, wc = warp & 1;
    const int b = blockIdx.y, k0 = blockIdx.x * 128;

    const float2* xp = reinterpret_cast<const float2*>(
        X + ((size_t)b * NN + k0) * FF);
    #pragma unroll
    for (int i = 0; i < 32; i++) {
        int idx = tid + 256 * i;             // 8192 float2
        int k = idx >> 6, f2i = idx & 63;
        float2 v = xp[(size_t)k * 64 + f2i];
        *reinterpret_cast<__half2*>(smx + k * PX_STRIDE + f2i * 2) =
            __float22half2_rn(v);
    }
    #pragma unroll
    for (int i = 0; i < 32; i++) {
        int idx = tid + 256 * i;             // 8192 float2
        int f = idx >> 6, n = (idx & 63) * 2;
        float2 v = *reinterpret_cast<const float2*>(w + (size_t)f * FF + n);
        smw[(n + 0) * PX_STRIDE + f] = __float2half_rn(v.x);
        smw[(n + 1) * PX_STRIDE + f] = __float2half_rn(v.y);
    }
    __syncthreads();

    float acc[2][8][4];
    #pragma unroll
    for (int mi = 0; mi < 2; mi++)
        #pragma unroll
        for (int ni = 0; ni < 8; ni++)
            #pragma unroll
            for (int q = 0; q < 4; q++) acc[mi][ni][q] = 0.f;

    #pragma unroll
    for (int ks = 0; ks < 8; ks++) {
        const int kk = ks * 16;
        uint32_t af[2][4];
        #pragma unroll
        for (int mi = 0; mi < 2; mi++) {
            const __half* ap = smx + (wr * 32 + mi * 16 + g) * PX_STRIDE + kk + 2 * t;
            af[mi][0] = *reinterpret_cast<const uint32_t*>(ap);
            af[mi][1] = *reinterpret_cast<const uint32_t*>(ap + 8 * PX_STRIDE);
            af[mi][2] = *reinterpret_cast<const uint32_t*>(ap + 8);
            af[mi][3] = *reinterpret_cast<const uint32_t*>(ap + 8 * PX_STRIDE + 8);
        }
        uint32_t bf[8][2];
        #pragma unroll
        for (int ni = 0; ni < 8; ni++) {
            const __half* bp = smw + (wc * 64 + ni * 8 + g) * PX_STRIDE + kk + 2 * t;
            bf[ni][0] = *reinterpret_cast<const uint32_t*>(bp);
            bf[ni][1] = *reinterpret_cast<const uint32_t*>(bp + 8);
        }
        #pragma unroll
        for (int mi = 0; mi < 2; mi++)
            #pragma unroll
            for (int ni = 0; ni < 8; ni++)
                MMA16(acc[mi][ni], af[mi], bf[ni]);
    }

    __half* xwg = g_xw + ((size_t)b * NN + k0) * FF;
    __syncthreads();                       // done reading smx -> reuse it
    #pragma unroll
    for (int mi = 0; mi < 2; mi++) {
        int r0 = wr * 32 + mi * 16 + g;
        #pragma unroll
        for (int ni = 0; ni < 8; ni++) {
            int n = wc * 64 + ni * 8 + 2 * t;
            __half2 h0 = __floats2half2_rn(acc[mi][ni][0], acc[mi][ni][1]);
            __half2 h1 = __floats2half2_rn(acc[mi][ni][2], acc[mi][ni][3]);
            *reinterpret_cast<__half2*>(xwg + (size_t)r0 * FF + n) = h0;
            *reinterpret_cast<__half2*>(xwg + (size_t)(r0 + 8) * FF + n) = h1;
            *reinterpret_cast<__half2*>(smx + r0 * PX_STRIDE + n) = h0;
            *reinterpret_cast<__half2*>(smx + (r0 + 8) * PX_STRIDE + n) = h1;
        }
    }
    __syncthreads();
    __half* xwtg = g_xwt + (size_t)b * FF * NN + k0;
    #pragma unroll
    for (int i = 0; i < 64; i++) {
        int idx = tid + 256 * i;             // 16384 halves
        int n = idx >> 7, kk = idx & 127;
        xwtg[(size_t)n * NN + kk] = smx[kk * PX_STRIDE + n];
    }
}

// ============================ main kernel ============================
// grid = 256 CTAs (4 batches x 64 M-tiles of 64 rows), 256 threads = 8 warps
// (2x4), warp tile 32(M) x 32(N). 5-stage cp.async pipeline, 2 CTAs/SM.
// Issue AFTER compute: keeps fragment LDS at the head of the L1tex queue.
__global__ void __launch_bounds__(256, 2)
graphconv_main(const float* __restrict__ A, float* __restrict__ out) {
    extern __shared__ __align__(16) char smc[];
    float* sm = reinterpret_cast<float*>(smc);
    const uint32_t sbase = smem_to_u32(smc);
    const int tid = threadIdx.x;
    const int lane = tid & 31, warp = tid >> 5;
    const int g = lane >> 2, t = lane & 3;
    const int wr = warp >> 2, wc = warp & 3;      // warp grid 2(M) x 4(N)
    const int bb = blockIdx.x >> 6;
    const int row0 = (blockIdx.x & 63) << 6;

    const float* Ab = A + (size_t)bb * NN * NN + (size_t)row0 * NN;
    const __half* Xwt = g_xwt + (size_t)bb * FF * NN;

    auto issue = [&](int chunk, int s) {
        const int k0 = chunk * KT;
        #pragma unroll
        for (int i = 0; i < 2; i++) {        // A: 64 rows x 128 B
            int c = tid + 256 * i, r = c >> 3, cc = c & 7;
            cp16(sbase + SM_A(s) + r * 160 + cc * 16,
                 Ab + (size_t)r * NN + k0 + cc * 4);
        }
        #pragma unroll
        for (int i = 0; i < 2; i++) {        // B: 128 rows x 64 B (fp16)
            int c = tid + 256 * i, r = c >> 2, cc = c & 3;
            cp16(sbase + SM_B(s) + r * 80 + cc * 16,
                 Xwt + (size_t)r * NN + k0 + cc * 8);
        }
        asm volatile("cp.async.commit_group;");
    };

    float acc[2][4][4];
    #pragma unroll
    for (int mi = 0; mi < 2; mi++)
        #pragma unroll
        for (int ni = 0; ni < 4; ni++)
            #pragma unroll
            for (int q = 0; q < 4; q++) acc[mi][ni][q] = 0.f;

    float dsum = 0.f;
    const int drow = tid >> 2, dq = tid & 3;

    issue(0, 0); issue(1, 1); issue(2, 2); issue(3, 3);

    int s = 0;
    for (int k = 0; k < KITERS; k++) {
        asm volatile("cp.async.wait_group %0;" :: "n"(NSTG - 2));
        __syncthreads();
        const float* sa = sm + (SM_A(s) >> 2);
        const __half* sb = reinterpret_cast<const __half*>(smc + SM_B(s));

        // deg partial row-sum (raw fp32 A) — quarter row per thread
        {
            const float4* dp =
                reinterpret_cast<const float4*>(sa + drow * 40 + dq * 8);
            float4 v0 = dp[0], v1 = dp[1];
            dsum += ((v0.x + v0.y) + (v0.z + v0.w)) +
                    ((v1.x + v1.y) + (v1.z + v1.w));
        }

        #pragma unroll
        for (int ks = 0; ks < 2; ks++) {
            const int kk = ks * 16;
            uint32_t af[2][4];
            #pragma unroll
            for (int mi = 0; mi < 2; mi++) {
                const float* ap = sa + (wr * 32 + mi * 16 + g) * 40 + kk + 2 * t;
                float2 v0 = *reinterpret_cast<const float2*>(ap);
                float2 v1 = *reinterpret_cast<const float2*>(ap + 8 * 40);
                float2 v2 = *reinterpret_cast<const float2*>(ap + 8);
                float2 v3 = *reinterpret_cast<const float2*>(ap + 8 * 40 + 8);
                af[mi][0] = packh2(v0.x, v0.y);
                af[mi][1] = packh2(v1.x, v1.y);
                af[mi][2] = packh2(v2.x, v2.y);
                af[mi][3] = packh2(v3.x, v3.y);
            }
            uint32_t bf[4][2];
            #pragma unroll
            for (int ni = 0; ni < 4; ni++) {
                const __half* bp = sb + (wc * 32 + ni * 8 + g) * 40 + kk + 2 * t;
                bf[ni][0] = *reinterpret_cast<const uint32_t*>(bp);
                bf[ni][1] = *reinterpret_cast<const uint32_t*>(bp + 8);
            }
            #pragma unroll
            for (int mi = 0; mi < 2; mi++)
                #pragma unroll
                for (int ni = 0; ni < 4; ni++)
                    MMA16(acc[mi][ni], af[mi], bf[ni]);
        }

        if (k + NSTG - 1 < KITERS) issue(k + NSTG - 1, (k + NSTG - 1) % NSTG);
        else asm volatile("cp.async.commit_group;");  // keep group count rolling

        if (++s == NSTG) s = 0;
    }

    // deg = rowsum(A) + 1 ; store reciprocal
    dsum += __shfl_xor_sync(0xffffffffu, dsum, 1);
    dsum += __shfl_xor_sync(0xffffffffu, dsum, 2);
    if (dq == 0) sm[(SM_DEG >> 2) + drow] = 1.0f / (dsum + 1.0f);
    __syncthreads();

    // out = relu(acc + Xw) * (1/deg)
    {
        float rc[2][2];
        #pragma unroll
        for (int mi = 0; mi < 2; mi++) {
            rc[mi][0] = sm[(SM_DEG >> 2) + wr * 32 + mi * 16 + g];
            rc[mi][1] = sm[(SM_DEG >> 2) + wr * 32 + mi * 16 + g + 8];
        }
        const __half* xwb = g_xw + ((size_t)bb * NN + row0) * FF;
        float* ob = out + ((size_t)bb * NN + row0) * FF;
        #pragma unroll
        for (int mi = 0; mi < 2; mi++) {
            int r0 = wr * 32 + mi * 16 + g;
            #pragma unroll
            for (int ni = 0; ni < 4; ni++) {
                int n = wc * 32 + ni * 8 + 2 * t;
                float2 x0 = __half22float2(*reinterpret_cast<const __half2*>(
                    xwb + (size_t)r0 * FF + n));
                float2 x1 = __half22float2(*reinterpret_cast<const __half2*>(
                    xwb + (size_t)(r0 + 8) * FF + n));
                float2 v0, v1;
                v0.x = fmaxf(acc[mi][ni][0] + x0.x, 0.f) * rc[mi][0];
                v0.y = fmaxf(acc[mi][ni][1] + x0.y, 0.f) * rc[mi][0];
                v1.x = fmaxf(acc[mi][ni][2] + x1.x, 0.f) * rc[mi][1];
                v1.y = fmaxf(acc[mi][ni][3] + x1.y, 0.f) * rc[mi][1];
                *reinterpret_cast<float2*>(ob + (size_t)r0 * FF + n) = v0;
                *reinterpret_cast<float2*>(ob + (size_t)(r0 + 8) * FF + n) = v1;
            }
        }
    }
}

// ============================ host ============================
extern "C" void kernel_launch(void* const* d_in, const int* in_sizes, int n_in,
                              void* d_out, int out_size) {
    const float* A = (const float*)d_in[0];   // relation_matrix [4,4096,4096]
    const float* X = (const float*)d_in[1];   // inputs          [4,4096,128]
    const float* w = (const float*)d_in[2];   // w               [128,128]
    float* out = (float*)d_out;               // [4,4096,128] fp32

    const int prep_smem = 2 * 128 * PX_STRIDE * 2;   // 69632 B
    cudaFuncSetAttribute(prep_xw_kernel,
                         cudaFuncAttributeMaxDynamicSharedMemorySize, prep_smem);
    cudaFuncSetAttribute(graphconv_main,
                         cudaFuncAttributeMaxDynamicSharedMemorySize, SMEM_MAIN);

    prep_xw_kernel<<<dim3(NN / 128, BB), 256, prep_smem>>>(X, w);
    graphconv_main<<<BB * 64, 256, SMEM_MAIN>>>(A, out);
}

// round 9
// speedup vs baseline: 2.2020x; 1.2959x over previous
#include <cuda_runtime.h>
#include <cuda_fp16.h>
#include <cstdint>

// ============================ problem constants ============================
#define BB 4
#define NN 4096
#define FF 128
#define KT 32                    // K per pipeline stage
#define NSTG 6
#define KITERS (NN / KT)         // 128

// ====================== main-kernel smem layout (bytes) ===================
// A stage: 128 rows x 40 floats (32 data + 8 pad) = 20480 B
// B stage: 128 rows x 40 halves (32 data + 8 pad) = 10240 B
#define STG_BYT   30720
#define SM_A(s)   ((s) * STG_BYT)
#define SM_B(s)   (SM_A(s) + 20480)
#define SMEM_MAIN (NSTG * STG_BYT)                 // 184320 B

// scratch (allocation-free rule: __device__ globals)
__device__ __align__(16) __half g_xw [(size_t)BB * NN * FF];  // Xw[b][k][n]
__device__ __align__(16) __half g_xwt[(size_t)BB * FF * NN];  // Xwt[b][n][k]

// ============================ helpers ============================
__device__ __forceinline__ uint32_t smem_to_u32(const void* p) {
    uint32_t a;
    asm("{ .reg .u64 tmp; cvta.to.shared.u64 tmp, %1; cvt.u32.u64 %0, tmp; }"
        : "=r"(a) : "l"(p));
    return a;
}

__device__ __forceinline__ void cp16(uint32_t s, const void* g) {
    asm volatile("cp.async.cg.shared.global [%0], [%1], 16;" :: "r"(s), "l"(g));
}

// pack two fp32 -> f16x2 reg, lo in low half (round-to-nearest-even)
__device__ __forceinline__ uint32_t packh2(float lo, float hi) {
    uint32_t r;
    asm("cvt.rn.f16x2.f32 %0, %1, %2;" : "=r"(r) : "f"(hi), "f"(lo));
    return r;
}

// D += A(16x16) * B(16x8), fp16 inputs, fp32 accum
#define MMA16(d, a, b) \
    asm volatile("mma.sync.aligned.m16n8k16.row.col.f32.f16.f16.f32 " \
        "{%0,%1,%2,%3}, {%4,%5,%6,%7}, {%8,%9}, {%0,%1,%2,%3};" \
        : "+f"((d)[0]), "+f"((d)[1]), "+f"((d)[2]), "+f"((d)[3]) \
        : "r"((a)[0]), "r"((a)[1]), "r"((a)[2]), "r"((a)[3]), \
          "r"((b)[0]), "r"((b)[1]))

// ============================ prep kernel (R5 proven) =====================
// Xw = X @ w (fp16 mma, fp32 accum); writes g_xw[b][k][n] and g_xwt[b][n][k].
// grid (32, BB), 256 threads = 8 warps (4x2), warp tile 32(k) x 64(n).
#define PX_STRIDE 136            // halves per row (128 data + 8 pad)
__global__ void __launch_bounds__(256, 1)
prep_xw_kernel(const float* __restrict__ X, const float* __restrict__ w) {
    extern __shared__ __align__(16) char psm[];
    __half* smx = reinterpret_cast<__half*>(psm);                   // X tile
    __half* smw = reinterpret_cast<__half*>(psm) + 128 * PX_STRIDE; // wt[n][f]
    const int tid = threadIdx.x;
    const int lane = tid & 31, warp = tid >> 5;
    const int g = lane >> 2, t = lane & 3;
    const int wr = warp >> 1, wc = warp & 1;
    const int b = blockIdx.y, k0 = blockIdx.x * 128;

    const float2* xp = reinterpret_cast<const float2*>(
        X + ((size_t)b * NN + k0) * FF);
    #pragma unroll
    for (int i = 0; i < 32; i++) {
        int idx = tid + 256 * i;             // 8192 float2
        int k = idx >> 6, f2i = idx & 63;
        float2 v = xp[(size_t)k * 64 + f2i];
        *reinterpret_cast<__half2*>(smx + k * PX_STRIDE + f2i * 2) =
            __float22half2_rn(v);
    }
    #pragma unroll
    for (int i = 0; i < 32; i++) {
        int idx = tid + 256 * i;             // 8192 float2
        int f = idx >> 6, n = (idx & 63) * 2;
        float2 v = *reinterpret_cast<const float2*>(w + (size_t)f * FF + n);
        smw[(n + 0) * PX_STRIDE + f] = __float2half_rn(v.x);
        smw[(n + 1) * PX_STRIDE + f] = __float2half_rn(v.y);
    }
    __syncthreads();

    float acc[2][8][4];
    #pragma unroll
    for (int mi = 0; mi < 2; mi++)
        #pragma unroll
        for (int ni = 0; ni < 8; ni++)
            #pragma unroll
            for (int q = 0; q < 4; q++) acc[mi][ni][q] = 0.f;

    #pragma unroll
    for (int ks = 0; ks < 8; ks++) {
        const int kk = ks * 16;
        uint32_t af[2][4];
        #pragma unroll
        for (int mi = 0; mi < 2; mi++) {
            const __half* ap = smx + (wr * 32 + mi * 16 + g) * PX_STRIDE + kk + 2 * t;
            af[mi][0] = *reinterpret_cast<const uint32_t*>(ap);
            af[mi][1] = *reinterpret_cast<const uint32_t*>(ap + 8 * PX_STRIDE);
            af[mi][2] = *reinterpret_cast<const uint32_t*>(ap + 8);
            af[mi][3] = *reinterpret_cast<const uint32_t*>(ap + 8 * PX_STRIDE + 8);
        }
        uint32_t bf[8][2];
        #pragma unroll
        for (int ni = 0; ni < 8; ni++) {
            const __half* bp = smw + (wc * 64 + ni * 8 + g) * PX_STRIDE + kk + 2 * t;
            bf[ni][0] = *reinterpret_cast<const uint32_t*>(bp);
            bf[ni][1] = *reinterpret_cast<const uint32_t*>(bp + 8);
        }
        #pragma unroll
        for (int mi = 0; mi < 2; mi++)
            #pragma unroll
            for (int ni = 0; ni < 8; ni++)
                MMA16(acc[mi][ni], af[mi], bf[ni]);
    }

    __half* xwg = g_xw + ((size_t)b * NN + k0) * FF;
    __syncthreads();                       // done reading smx -> reuse it
    #pragma unroll
    for (int mi = 0; mi < 2; mi++) {
        int r0 = wr * 32 + mi * 16 + g;
        #pragma unroll
        for (int ni = 0; ni < 8; ni++) {
            int n = wc * 64 + ni * 8 + 2 * t;
            __half2 h0 = __floats2half2_rn(acc[mi][ni][0], acc[mi][ni][1]);
            __half2 h1 = __floats2half2_rn(acc[mi][ni][2], acc[mi][ni][3]);
            *reinterpret_cast<__half2*>(xwg + (size_t)r0 * FF + n) = h0;
            *reinterpret_cast<__half2*>(xwg + (size_t)(r0 + 8) * FF + n) = h1;
            *reinterpret_cast<__half2*>(smx + r0 * PX_STRIDE + n) = h0;
            *reinterpret_cast<__half2*>(smx + (r0 + 8) * PX_STRIDE + n) = h1;
        }
    }
    __syncthreads();
    __half* xwtg = g_xwt + (size_t)b * FF * NN + k0;
    #pragma unroll
    for (int i = 0; i < 64; i++) {
        int idx = tid + 256 * i;             // 16384 halves
        int n = idx >> 7, kk = idx & 127;
        xwtg[(size_t)n * NN + kk] = smx[kk * PX_STRIDE + n];
    }
}

// ============================ main kernel ============================
// grid = 128 CTAs (4 batches x 32 M-tiles), 256 threads = 8 warps (4x2),
// warp tile 32(M) x 64(N). 6-stage cp.async pipeline, issue after compute.
// deg is accumulated from the A fragments already loaded for the MMA —
// no separate smem pass (saves 16 KB/stage of L1 traffic + one barrier).
__global__ void __launch_bounds__(256, 1)
graphconv_main(const float* __restrict__ A, float* __restrict__ out) {
    extern __shared__ __align__(16) char smc[];
    float* sm = reinterpret_cast<float*>(smc);
    const uint32_t sbase = smem_to_u32(smc);
    const int tid = threadIdx.x;
    const int lane = tid & 31, warp = tid >> 5;
    const int g = lane >> 2, t = lane & 3;
    const int wr = warp >> 1, wc = warp & 1;      // warp grid 4(M) x 2(N)
    const int bb = blockIdx.x >> 5;
    const int row0 = (blockIdx.x & 31) << 7;

    const float* Ab = A + (size_t)bb * NN * NN + (size_t)row0 * NN;
    const __half* Xwt = g_xwt + (size_t)bb * FF * NN;

    auto issue = [&](int chunk, int s) {
        const int k0 = chunk * KT;
        #pragma unroll
        for (int i = 0; i < 4; i++) {        // A: 128 rows x 128 B
            int c = tid + 256 * i, r = c >> 3, cc = c & 7;
            cp16(sbase + SM_A(s) + r * 160 + cc * 16,
                 Ab + (size_t)r * NN + k0 + cc * 4);
        }
        #pragma unroll
        for (int i = 0; i < 2; i++) {        // B: 128 rows x 64 B (fp16)
            int c = tid + 256 * i, r = c >> 2, cc = c & 3;
            cp16(sbase + SM_B(s) + r * 80 + cc * 16,
                 Xwt + (size_t)r * NN + k0 + cc * 8);
        }
        asm volatile("cp.async.commit_group;");
    };

    float acc[2][8][4];
    #pragma unroll
    for (int mi = 0; mi < 2; mi++)
        #pragma unroll
        for (int ni = 0; ni < 8; ni++)
            #pragma unroll
            for (int q = 0; q < 4; q++) acc[mi][ni][q] = 0.f;

    float dsum[2][2] = {{0.f, 0.f}, {0.f, 0.f}};   // [mi][row / row+8]

    #pragma unroll
    for (int p = 0; p < NSTG - 1; p++) issue(p, p);

    int s = 0;
    for (int k = 0; k < KITERS; k++) {
        asm volatile("cp.async.wait_group %0;" :: "n"(NSTG - 2));
        __syncthreads();
        const float* sa = sm + (SM_A(s) >> 2);
        const __half* sb = reinterpret_cast<const __half*>(smc + SM_B(s));

        #pragma unroll
        for (int ks = 0; ks < 2; ks++) {
            const int kk = ks * 16;
            uint32_t af[2][4];
            #pragma unroll
            for (int mi = 0; mi < 2; mi++) {
                const float* ap = sa + (wr * 32 + mi * 16 + g) * 40 + kk + 2 * t;
                float2 v0 = *reinterpret_cast<const float2*>(ap);
                float2 v1 = *reinterpret_cast<const float2*>(ap + 8 * 40);
                float2 v2 = *reinterpret_cast<const float2*>(ap + 8);
                float2 v3 = *reinterpret_cast<const float2*>(ap + 8 * 40 + 8);
                dsum[mi][0] += (v0.x + v0.y) + (v2.x + v2.y);
                dsum[mi][1] += (v1.x + v1.y) + (v3.x + v3.y);
                af[mi][0] = packh2(v0.x, v0.y);
                af[mi][1] = packh2(v1.x, v1.y);
                af[mi][2] = packh2(v2.x, v2.y);
                af[mi][3] = packh2(v3.x, v3.y);
            }
            uint32_t bf[8][2];
            #pragma unroll
            for (int ni = 0; ni < 8; ni++) {
                const __half* bp = sb + (wc * 64 + ni * 8 + g) * 40 + kk + 2 * t;
                bf[ni][0] = *reinterpret_cast<const uint32_t*>(bp);
                bf[ni][1] = *reinterpret_cast<const uint32_t*>(bp + 8);
            }
            #pragma unroll
            for (int mi = 0; mi < 2; mi++)
                #pragma unroll
                for (int ni = 0; ni < 8; ni++)
                    MMA16(acc[mi][ni], af[mi], bf[ni]);
        }

        if (k + NSTG - 1 < KITERS) issue(k + NSTG - 1, (k + NSTG - 1) % NSTG);
        else asm volatile("cp.async.commit_group;");  // keep group count rolling

        if (++s == NSTG) s = 0;
    }

    // deg: each thread's fragments covered k = {2t,2t+1,8+2t,8+2t+1} per k16
    // step for its rows; reduce over the 4 t-lanes to get the full row sum.
    float rc[2][2];
    #pragma unroll
    for (int mi = 0; mi < 2; mi++)
        #pragma unroll
        for (int j = 0; j < 2; j++) {
            float v = dsum[mi][j];
            v += __shfl_xor_sync(0xffffffffu, v, 1);
            v += __shfl_xor_sync(0xffffffffu, v, 2);
            rc[mi][j] = 1.0f / (v + 1.0f);            // deg = rowsum(A) + 1
        }

    // out = relu(acc + Xw) * (1/deg)
    {
        const __half* xwb = g_xw + ((size_t)bb * NN + row0) * FF;
        float* ob = out + ((size_t)bb * NN + row0) * FF;
        #pragma unroll
        for (int mi = 0; mi < 2; mi++) {
            int r0 = wr * 32 + mi * 16 + g;
            #pragma unroll
            for (int ni = 0; ni < 8; ni++) {
                int n = wc * 64 + ni * 8 + 2 * t;
                float2 x0 = __half22float2(*reinterpret_cast<const __half2*>(
                    xwb + (size_t)r0 * FF + n));
                float2 x1 = __half22float2(*reinterpret_cast<const __half2*>(
                    xwb + (size_t)(r0 + 8) * FF + n));
                float2 v0, v1;
                v0.x = fmaxf(acc[mi][ni][0] + x0.x, 0.f) * rc[mi][0];
                v0.y = fmaxf(acc[mi][ni][1] + x0.y, 0.f) * rc[mi][0];
                v1.x = fmaxf(acc[mi][ni][2] + x1.x, 0.f) * rc[mi][1];
                v1.y = fmaxf(acc[mi][ni][3] + x1.y, 0.f) * rc[mi][1];
                *reinterpret_cast<float2*>(ob + (size_t)r0 * FF + n) = v0;
                *reinterpret_cast<float2*>(ob + (size_t)(r0 + 8) * FF + n) = v1;
            }
        }
    }
}

// ============================ host ============================
extern "C" void kernel_launch(void* const* d_in, const int* in_sizes, int n_in,
                              void* d_out, int out_size) {
    const float* A = (const float*)d_in[0];   // relation_matrix [4,4096,4096]
    const float* X = (const float*)d_in[1];   // inputs          [4,4096,128]
    const float* w = (const float*)d_in[2];   // w               [128,128]
    float* out = (float*)d_out;               // [4,4096,128] fp32

    const int prep_smem = 2 * 128 * PX_STRIDE * 2;   // 69632 B
    cudaFuncSetAttribute(prep_xw_kernel,
                         cudaFuncAttributeMaxDynamicSharedMemorySize, prep_smem);
    cudaFuncSetAttribute(graphconv_main,
                         cudaFuncAttributeMaxDynamicSharedMemorySize, SMEM_MAIN);

    prep_xw_kernel<<<dim3(NN / 128, BB), 256, prep_smem>>>(X, w);
    graphconv_main<<<BB * 32, 256, SMEM_MAIN>>>(A, out);
}